// round 6
// baseline (speedup 1.0000x reference)
#include <cuda_runtime.h>
#include <math.h>

#define BB 16
#define SS 512
#define DD 512
#define VV 32000
#define KK 4
#define TT 64
#define NR (BB*KK)     // 64 rows
#define NCG (VV/256)   // 125 vocab col-groups of 256
#define SOS_TOK 1
#define EOS_TOK 2
#define PAD_TOK 0
#define NEGV (-1e9f)

// ---------------- device state ----------------
__device__ float g_encK[BB*SS*DD];     // [b][s][d]  (16.8 MB)
__device__ float g_embQ[VV*DD];        // emb @ Wq   (65.5 MB)
__device__ float g_att[NR*SS];         // raw masked scaled scores
__device__ float g_hT[DD*NR];          // [d][row]
__device__ float g_pmax[NR*NCG];
__device__ float g_psum[NR*NCG];
__device__ float g_pval[NR*NCG*4];
__device__ int   g_pidx[NR*NCG*4];
__device__ int   g_tok[NR];
__device__ float g_scores[NR];
__device__ int   g_finished[NR];
__device__ int   g_seqs[BB*KK*TT];

__device__ __forceinline__ bool better(float xv, int xi, float yv, int yi) {
    return (xv > yv) || (xv == yv && xi < yi);
}

#define FMA2(acc,a,b) asm("fma.rn.f32x2 %0, %1, %2, %3;" : "=l"(acc) : "l"(a), "l"(b), "l"(acc))
#define PACK2(d,x,y)  asm("mov.b64 %0, {%1, %2};" : "=l"(d) : "f"(x), "f"(y))
#define UNPACK2(x,y,d) asm("mov.b64 {%0, %1}, %2;" : "=f"(x), "=f"(y) : "l"(d))

__device__ __forceinline__ void merge4(float av[4], int ai[4], const float bv[4], const int bi[4]) {
    float ov[4]; int oi[4]; int i = 0, j = 0;
    #pragma unroll
    for (int o = 0; o < 4; ++o) {
        bool ta = (j >= 4) || (i < 4 && better(av[i], ai[i], bv[j], bi[j]));
        if (ta) { ov[o] = av[i]; oi[o] = ai[i]; ++i; }
        else    { ov[o] = bv[j]; oi[o] = bi[j]; ++j; }
    }
    #pragma unroll
    for (int o = 0; o < 4; ++o) { av[o] = ov[o]; ai[o] = oi[o]; }
}

__device__ __forceinline__ void insert4(float av[4], int ai[4], float x, int xi) {
    if (better(x, xi, av[3], ai[3])) {
        if (better(x, xi, av[0], ai[0]))      { av[3]=av[2];ai[3]=ai[2]; av[2]=av[1];ai[2]=ai[1]; av[1]=av[0];ai[1]=ai[0]; av[0]=x;ai[0]=xi; }
        else if (better(x, xi, av[1], ai[1])) { av[3]=av[2];ai[3]=ai[2]; av[2]=av[1];ai[2]=ai[1]; av[1]=x;ai[1]=xi; }
        else if (better(x, xi, av[2], ai[2])) { av[3]=av[2];ai[3]=ai[2]; av[2]=x;ai[2]=xi; }
        else                                  { av[3]=x;ai[3]=xi; }
    }
}

// ---------------- generic 128x128 tile SGEMM (K=512, N=512), f32x2 inner ----------------
__global__ void __launch_bounds__(256) gemm_kernel(const float* __restrict__ A,
                                                   const float* __restrict__ B,
                                                   int which) {
    float* C = which ? g_embQ : g_encK;
    __shared__ float As[32][132];   // [k][m]
    __shared__ float Bs[32][132];   // [k][n]
    int n0 = blockIdx.x * 128;
    int m0 = blockIdx.y * 128;
    int t = threadIdx.x;
    int tx = t & 15, ty = t >> 4;
    unsigned long long acc2[8][4];
    #pragma unroll
    for (int i = 0; i < 8; ++i)
        #pragma unroll
        for (int j = 0; j < 4; ++j) acc2[i][j] = 0ull;

    for (int k0 = 0; k0 < 512; k0 += 32) {
        #pragma unroll
        for (int i = 0; i < 4; ++i) {
            int idx = t + i*256;
            int mi = idx >> 3, kq = idx & 7;
            float4 f = *(const float4*)(A + (size_t)(m0 + mi)*512 + k0 + kq*4);
            As[kq*4+0][mi] = f.x; As[kq*4+1][mi] = f.y; As[kq*4+2][mi] = f.z; As[kq*4+3][mi] = f.w;
        }
        #pragma unroll
        for (int i = 0; i < 4; ++i) {
            int idx = t + i*256;
            int kk = idx >> 5, nq = idx & 31;
            *(float4*)(&Bs[kk][nq*4]) = *(const float4*)(B + (size_t)(k0+kk)*512 + n0 + nq*4);
        }
        __syncthreads();
        #pragma unroll 4
        for (int kk = 0; kk < 32; ++kk) {
            float a[8];
            *(float4*)(a)   = *(const float4*)(&As[kk][ty*8]);
            *(float4*)(a+4) = *(const float4*)(&As[kk][ty*8+4]);
            const unsigned long long* wp = (const unsigned long long*)(&Bs[kk][tx*8]);
            unsigned long long w0 = wp[0], w1 = wp[1], w2 = wp[2], w3 = wp[3];
            #pragma unroll
            for (int i = 0; i < 8; ++i) {
                unsigned long long a2; PACK2(a2, a[i], a[i]);
                FMA2(acc2[i][0], a2, w0);
                FMA2(acc2[i][1], a2, w1);
                FMA2(acc2[i][2], a2, w2);
                FMA2(acc2[i][3], a2, w3);
            }
        }
        __syncthreads();
    }
    #pragma unroll
    for (int i = 0; i < 8; ++i) {
        float o[8];
        #pragma unroll
        for (int j = 0; j < 4; ++j) { UNPACK2(o[2*j], o[2*j+1], acc2[i][j]); }
        float* dst = C + (size_t)(m0 + ty*8 + i)*512 + n0 + tx*8;
        *(float4*)dst = *(float4*)(o);
        *(float4*)(dst+4) = *(float4*)(o+4);
    }
}

__global__ void init_kernel() {
    int t = threadIdx.x;   // 64
    g_tok[t] = SOS_TOK;
    g_finished[t] = 0;
    g_scores[t] = 0.f;
}

// ---------------- scores: grid (8 s-chunks, 16 b); 4 beams share each k-vector load ----------------
__global__ void __launch_bounds__(256) score_kernel(const int* __restrict__ lens) {
    int c = blockIdx.x;            // 64-s chunk
    int b = blockIdx.y;
    int t = threadIdx.x;
    int w = t >> 5, lane = t & 31;
    __shared__ float q_s[KK][DD];  // 8 KB
    __shared__ int toks[KK];
    __shared__ int slen;
    if (t < KK) toks[t] = g_tok[b*KK + t];
    if (t == 0) slen = lens[b];
    __syncthreads();
    for (int i = t; i < KK*DD; i += 256) {
        int k = i >> 9, d = i & 511;
        q_s[k][d] = g_embQ[(size_t)toks[k]*DD + d];
    }
    __syncthreads();

    int sbase = c*64 + w*8;        // this warp's 8 s-positions
    const float* kp = g_encK + ((size_t)b*SS + sbase)*DD + lane;
    float acc[8][4];
    #pragma unroll
    for (int s = 0; s < 8; ++s) { acc[s][0]=0.f; acc[s][1]=0.f; acc[s][2]=0.f; acc[s][3]=0.f; }

    #pragma unroll
    for (int j = 0; j < 16; ++j) {
        float kv[8];
        #pragma unroll
        for (int s = 0; s < 8; ++s) kv[s] = kp[(size_t)s*DD + 32*j];
        float q0 = q_s[0][lane+32*j], q1 = q_s[1][lane+32*j],
              q2 = q_s[2][lane+32*j], q3 = q_s[3][lane+32*j];
        #pragma unroll
        for (int s = 0; s < 8; ++s) {
            acc[s][0] = fmaf(q0, kv[s], acc[s][0]);
            acc[s][1] = fmaf(q1, kv[s], acc[s][1]);
            acc[s][2] = fmaf(q2, kv[s], acc[s][2]);
            acc[s][3] = fmaf(q3, kv[s], acc[s][3]);
        }
    }
    #pragma unroll
    for (int s = 0; s < 8; ++s)
        #pragma unroll
        for (int k = 0; k < 4; ++k)
            #pragma unroll
            for (int off = 16; off > 0; off >>= 1)
                acc[s][k] += __shfl_xor_sync(0xffffffffu, acc[s][k], off);

    float myv = 0.f;
    #pragma unroll
    for (int s = 0; s < 8; ++s)
        #pragma unroll
        for (int k = 0; k < 4; ++k)
            if (lane == s*4 + k) myv = acc[s][k];
    int s = sbase + (lane >> 2);
    int k = lane & 3;
    const float scale = 0.044194173824159216f;  // 1/sqrt(512)
    g_att[(size_t)(b*KK + k)*SS + s] = (s < slen) ? myv*scale : NEGV;
}

// ---------------- ctx: grid (8 d-chunks, 16 b); redundant cheap softmax + shared enc reads ----------------
__global__ void __launch_bounds__(256) ctx_kernel(const float* __restrict__ enc,
                                                  const float* __restrict__ emb) {
    int dc = blockIdx.x;   // 64-dim chunk
    int b = blockIdx.y;
    int t = threadIdx.x;
    int w = t >> 5, lane = t & 31;
    __shared__ float p_s[SS][KK];      // probs packed [s][k] -> one LDS.128 per s
    __shared__ float sredm[8], sreds[8];
    __shared__ float inv_s[KK];
    __shared__ int toks[KK];
    __shared__ float cred[4][64][4];   // [sgroup][dim][k]
    if (t < KK) toks[t] = g_tok[b*KK + t];

    // phase 1: softmax; warp w -> beam w>>1, s-half w&1
    int kb = w >> 1, hh = w & 1;
    const float* arow = g_att + (size_t)(b*KK + kb)*SS + hh*256 + lane;
    float x[8];
    #pragma unroll
    for (int j = 0; j < 8; ++j) x[j] = arow[32*j];
    float m = x[0];
    #pragma unroll
    for (int j = 1; j < 8; ++j) m = fmaxf(m, x[j]);
    #pragma unroll
    for (int off = 16; off > 0; off >>= 1) m = fmaxf(m, __shfl_xor_sync(0xffffffffu, m, off));
    if (lane == 0) sredm[w] = m;
    __syncthreads();
    float mk = fmaxf(sredm[kb*2], sredm[kb*2+1]);
    float sum = 0.f;
    #pragma unroll
    for (int j = 0; j < 8; ++j) {
        float e = expf(x[j] - mk);
        p_s[hh*256 + lane + 32*j][kb] = e;
        sum += e;
    }
    #pragma unroll
    for (int off = 16; off > 0; off >>= 1) sum += __shfl_xor_sync(0xffffffffu, sum, off);
    if (lane == 0) sreds[w] = sum;
    __syncthreads();
    if (t < KK) inv_s[t] = 1.f / (sreds[t*2] + sreds[t*2+1]);
    __syncthreads();

    // phase 2: ctx partials; thread = (dim t&63, s-group t>>6 covering 128 s)
    int d = dc*64 + (t & 63);
    int sg = t >> 6;
    const float* ep = enc + ((size_t)b*SS + sg*128)*DD + d;
    float a0=0.f, a1=0.f, a2=0.f, a3=0.f;
    #pragma unroll 8
    for (int i = 0; i < 128; ++i) {
        float ev = ep[(size_t)i*DD];
        float4 p = *(const float4*)(&p_s[sg*128 + i][0]);
        a0 = fmaf(p.x, ev, a0);
        a1 = fmaf(p.y, ev, a1);
        a2 = fmaf(p.z, ev, a2);
        a3 = fmaf(p.w, ev, a3);
    }
    *(float4*)(&cred[sg][t & 63][0]) = make_float4(a0, a1, a2, a3);
    __syncthreads();
    if (t < 64) {
        float4 c0 = *(float4*)(&cred[0][t][0]);
        float4 c1 = *(float4*)(&cred[1][t][0]);
        float4 c2 = *(float4*)(&cred[2][t][0]);
        float4 c3 = *(float4*)(&cred[3][t][0]);
        int dd = dc*64 + t;
        float4 out;
        out.x = emb[(size_t)toks[0]*DD + dd] + (c0.x+c1.x+c2.x+c3.x)*inv_s[0];
        out.y = emb[(size_t)toks[1]*DD + dd] + (c0.y+c1.y+c2.y+c3.y)*inv_s[1];
        out.z = emb[(size_t)toks[2]*DD + dd] + (c0.z+c1.z+c2.z+c3.z)*inv_s[2];
        out.w = emb[(size_t)toks[3]*DD + dd] + (c0.w+c1.w+c2.w+c3.w)*inv_s[3];
        *(float4*)(&g_hT[dd*NR + b*KK]) = out;
    }
}

// ---------------- logits GEMM (f32x2) + fused per-block reduction ----------------
__global__ void __launch_bounds__(256) logits_kernel(const float* __restrict__ Wfc,
                                                     const float* __restrict__ bfc) {
    __shared__ float h_s[DD*16];           // [d][16 rows] = 32 KB
    int rg = blockIdx.x & 3;
    int cg = blockIdx.x >> 2;
    int t = threadIdx.x;

    for (int i = t; i < DD*16; i += 256) {
        int d = i >> 4, r = i & 15;
        h_s[i] = g_hT[d*NR + rg*16 + r];
    }
    __syncthreads();

    int v = cg*256 + t;
    float bias = bfc[v];
    unsigned long long acc[8];
    unsigned long long bias2; PACK2(bias2, bias, bias);
    #pragma unroll
    for (int j = 0; j < 8; ++j) acc[j] = bias2;

    for (int d0 = 0; d0 < DD; d0 += 8) {
        float w[8];
        #pragma unroll
        for (int j = 0; j < 8; ++j) w[j] = Wfc[(size_t)(d0+j)*VV + v];
        #pragma unroll
        for (int j = 0; j < 8; ++j) {
            unsigned long long w2; PACK2(w2, w[j], w[j]);
            const ulonglong2* hp = (const ulonglong2*)(h_s + (d0+j)*16);
            ulonglong2 p0 = hp[0], p1 = hp[1], p2 = hp[2], p3 = hp[3];
            FMA2(acc[0], p0.x, w2); FMA2(acc[1], p0.y, w2);
            FMA2(acc[2], p1.x, w2); FMA2(acc[3], p1.y, w2);
            FMA2(acc[4], p2.x, w2); FMA2(acc[5], p2.y, w2);
            FMA2(acc[6], p3.x, w2); FMA2(acc[7], p3.y, w2);
        }
    }

    float vals[16];
    #pragma unroll
    for (int j = 0; j < 8; ++j) { float lo, hi; UNPACK2(lo, hi, acc[j]); vals[2*j] = lo; vals[2*j+1] = hi; }

    __syncthreads();
    float* sv = h_s;                        // [16][257]
    #pragma unroll
    for (int r = 0; r < 16; ++r) sv[r*257 + t] = vals[r];
    __syncthreads();

    int w = t >> 5, l = t & 31;
    #pragma unroll
    for (int rr = 0; rr < 2; ++rr) {
        int r = w*2 + rr;
        float x[8]; int xi[8];
        #pragma unroll
        for (int i = 0; i < 8; ++i) { x[i] = sv[r*257 + l + 32*i]; xi[i] = cg*256 + l + 32*i; }
        float m = x[0];
        #pragma unroll
        for (int i = 1; i < 8; ++i) m = fmaxf(m, x[i]);
        #pragma unroll
        for (int off = 16; off > 0; off >>= 1) m = fmaxf(m, __shfl_xor_sync(0xffffffffu, m, off));
        float s = 0.f;
        #pragma unroll
        for (int i = 0; i < 8; ++i) s += expf(x[i] - m);
        #pragma unroll
        for (int off = 16; off > 0; off >>= 1) s += __shfl_xor_sync(0xffffffffu, s, off);
        float tv[4] = {-3.4e38f, -3.4e38f, -3.4e38f, -3.4e38f};
        int   ti[4] = {0x7fffffff, 0x7fffffff, 0x7fffffff, 0x7fffffff};
        #pragma unroll
        for (int i = 0; i < 8; ++i) insert4(tv, ti, x[i], xi[i]);
        #pragma unroll
        for (int off = 16; off > 0; off >>= 1) {
            float bv[4]; int bi[4];
            #pragma unroll
            for (int j = 0; j < 4; ++j) {
                bv[j] = __shfl_xor_sync(0xffffffffu, tv[j], off);
                bi[j] = __shfl_xor_sync(0xffffffffu, ti[j], off);
            }
            merge4(tv, ti, bv, bi);
        }
        if (l == 0) {
            int grow = rg*16 + r;
            int p = grow*NCG + cg;
            g_pmax[p] = m;
            g_psum[p] = s;
            #pragma unroll
            for (int j = 0; j < 4; ++j) { g_pval[p*4+j] = tv[j]; g_pidx[p*4+j] = ti[j]; }
        }
    }
}

// ---------------- merge partials + beam combine ----------------
__global__ void __launch_bounds__(128) combine_kernel(int tstep) {
    int b = blockIdx.x;
    int t = threadIdx.x;
    int w = t >> 5, l = t & 31;
    __shared__ float s_lse[KK];
    __shared__ float s_tv[KK][KK];
    __shared__ int   s_ti[KK][KK];
    __shared__ int   nbeam[KK], ntok[KK], nfin[KK];
    __shared__ float nsc[KK];
    __shared__ int   oldseq[KK][TT];
    __shared__ int   oldfin[KK];
    __shared__ float oldsc[KK];

    {
        int row = b*KK + w;
        float m = -3.4e38f, s = 0.f;
        float tv[4] = {-3.4e38f, -3.4e38f, -3.4e38f, -3.4e38f};
        int   ti[4] = {0x7fffffff, 0x7fffffff, 0x7fffffff, 0x7fffffff};
        for (int c = l; c < NCG; c += 32) {
            int p = row*NCG + c;
            float pm = g_pmax[p], ps = g_psum[p];
            float M = fmaxf(m, pm);
            s = s*expf(m - M) + ps*expf(pm - M);
            m = M;
            float bv[4]; int bi[4];
            #pragma unroll
            for (int j = 0; j < 4; ++j) { bv[j] = g_pval[p*4+j]; bi[j] = g_pidx[p*4+j]; }
            merge4(tv, ti, bv, bi);
        }
        #pragma unroll
        for (int off = 16; off > 0; off >>= 1) {
            float pm = __shfl_xor_sync(0xffffffffu, m, off);
            float ps = __shfl_xor_sync(0xffffffffu, s, off);
            float M = fmaxf(m, pm);
            s = s*expf(m - M) + ps*expf(pm - M);
            m = M;
            float bv[4]; int bi[4];
            #pragma unroll
            for (int j = 0; j < 4; ++j) {
                bv[j] = __shfl_xor_sync(0xffffffffu, tv[j], off);
                bi[j] = __shfl_xor_sync(0xffffffffu, ti[j], off);
            }
            merge4(tv, ti, bv, bi);
        }
        if (l == 0) {
            s_lse[w] = m + logf(s);
            #pragma unroll
            for (int j = 0; j < 4; ++j) { s_tv[w][j] = tv[j]; s_ti[w][j] = ti[j]; }
        }
    }

    if (t < KK) { oldfin[t] = g_finished[b*KK + t]; oldsc[t] = g_scores[b*KK + t]; }
    for (int i = t; i < KK*TT; i += 128) oldseq[i >> 6][i & 63] = g_seqs[b*KK*TT + i];
    __syncthreads();

    if (tstep == 1) {
        if (t < KK) {
            int tok = s_ti[0][t];
            g_scores[b*KK + t]   = s_tv[0][t] - s_lse[0];
            g_tok[b*KK + t]      = tok;
            g_finished[b*KK + t] = (tok == EOS_TOK) ? 1 : 0;
        }
        for (int i = t; i < KK*TT; i += 128) {
            int k = i >> 6, j = i & 63;
            int v = (j == 0) ? SOS_TOK : (j == 1 ? s_ti[0][k] : PAD_TOK);
            g_seqs[b*KK*TT + i] = v;
        }
        return;
    }

    if (t == 0) {
        float cl[KK*KK]; int cv[KK*KK];
        for (int k = 0; k < KK; ++k) {
            if (oldfin[k]) {
                cl[k*KK+0] = 0.f; cv[k*KK+0] = PAD_TOK;
                for (int j = 1; j < KK; ++j) { cl[k*KK+j] = NEGV; cv[k*KK+j] = PAD_TOK; }
            } else {
                for (int j = 0; j < KK; ++j) {
                    cl[k*KK+j] = s_tv[k][j] - s_lse[k];
                    cv[k*KK+j] = s_ti[k][j];
                }
            }
        }
        float total[KK*KK];
        for (int i = 0; i < KK*KK; ++i) total[i] = oldsc[i >> 2] + cl[i];
        bool used[KK*KK] = {false};
        for (int k = 0; k < KK; ++k) {
            int best = -1;
            for (int i = 0; i < KK*KK; ++i)
                if (!used[i] && (best < 0 || total[i] > total[best])) best = i;
            used[best] = true;
            int beam = best >> 2;
            nbeam[k] = beam;
            ntok[k]  = cv[best];
            nsc[k]   = total[best];
            nfin[k]  = oldfin[beam] | (cv[best] == EOS_TOK ? 1 : 0);
        }
    }
    __syncthreads();

    if (t < KK) {
        g_scores[b*KK + t]   = nsc[t];
        g_finished[b*KK + t] = nfin[t];
        g_tok[b*KK + t]      = ntok[t];
    }
    for (int i = t; i < KK*TT; i += 128) {
        int k = i >> 6, j = i & 63;
        g_seqs[b*KK*TT + i] = (j == tstep) ? ntok[k] : oldseq[nbeam[k]][j];
    }
}

// ---------------- output ----------------
__global__ void out_kernel(float* __restrict__ out, int out_size) {
    int b = blockIdx.x;     // 16
    int t = threadIdx.x;    // 64
    __shared__ int best;
    __shared__ float bestsc;
    if (t == 0) {
        int bi = 0; float bs = g_scores[b*KK];
        for (int k = 1; k < KK; ++k)
            if (g_scores[b*KK + k] > bs) { bs = g_scores[b*KK + k]; bi = k; }
        best = bi; bestsc = bs;
    }
    __syncthreads();
    if (out_size >= BB*TT + BB) {
        out[b*TT + t] = (float)g_seqs[b*KK*TT + best*TT + t];
        if (t == 0) out[BB*TT + b] = bestsc;
    } else if (out_size == BB*TT) {
        out[b*TT + t] = (float)g_seqs[b*KK*TT + best*TT + t];
    } else if (out_size == BB) {
        if (t == 0) out[b] = bestsc;
    }
}

// ---------------- launcher ----------------
extern "C" void kernel_launch(void* const* d_in, const int* in_sizes, int n_in,
                              void* d_out, int out_size) {
    const float* enc  = (const float*)d_in[0];
    const int*   lens = (const int*)  d_in[1];
    const float* emb  = (const float*)d_in[2];
    const float* Wq   = (const float*)d_in[3];
    const float* Wk   = (const float*)d_in[4];
    const float* Wfc  = (const float*)d_in[5];
    const float* bfc  = (const float*)d_in[6];

    gemm_kernel<<<dim3(4, 64), 256>>>(enc, Wk, 0);     // encK = enc @ Wk   [b][s][d]
    gemm_kernel<<<dim3(4, 250), 256>>>(emb, Wq, 1);    // embQ = emb @ Wq
    init_kernel<<<1, 64>>>();

    for (int step = 1; step < TT; ++step) {
        score_kernel<<<dim3(8, BB), 256>>>(lens);
        ctx_kernel<<<dim3(8, BB), 256>>>(enc, emb);
        logits_kernel<<<4*NCG, 256>>>(Wfc, bfc);
        combine_kernel<<<BB, 128>>>(step);
    }

    out_kernel<<<BB, 64>>>((float*)d_out, out_size);
}